// round 14
// baseline (speedup 1.0000x reference)
#include <cuda_runtime.h>
#include <cuda_fp16.h>
#include <cstdint>
#include <math.h>

#define N_TIME   512
#define LATENT   32
#define HIDDEN   64
#define N_MODES  8
#define X_A0     0.3f
#define CSANMAX  28700.0f
#define BASE_LOGIT (-0.8472978603872034f)
#define PI_F 3.14159265358979323846f

#define TPB       128
#define M_TILE    128
#define GRID_CTAS 592

#define EMB_STRIDE_B  64   // bytes per emb row (32 fp16); 16B-aligned for ldmatrix
#define TRIG_STRIDE_B 48   // bytes per trig row; 16B-aligned, conflict-free

// ---- smem layout (bytes) ----
#define SM_EMB  0                          // 511 * 64 -> pad 32768
#define SM_TRIG 32768                      // 128 * 48 = 6144
#define SM_F0H  (SM_TRIG + 6144)           // 38912, 3ks*4ntp*32*16 = 6144
#define SM_F1H  (SM_F0H + 6144)            // 45056, 4ks -> 8192
#define SM_B0   (SM_F1H + 8192)            // 53248
#define SM_B1   (SM_B0 + 256)
#define SM_WO   (SM_B1 + 256)
#define SM_W48  (SM_WO + 256)              // W0 row 48 (fp32)
#define SM_BO   (SM_W48 + 256)
#define SM_TOTAL (SM_BO + 16)              // 54288 (~53 KB) -> 4 CTAs/SM

typedef uint32_t u32;

#define HALF2_HALF 0x38003800u   // fp16x2 {0.5, 0.5}

__device__ __forceinline__ u32 smem_u32(const void* p) {
    u32 a;
    asm("{ .reg .u64 t; cvta.to.shared.u64 t, %1; cvt.u32.u64 %0, t; }"
        : "=r"(a) : "l"(p));
    return a;
}

// pack two fp32 -> fp16x2, first arg in LOW half
__device__ __forceinline__ u32 pk16(float lo, float hi) {
    u32 r;
    asm("cvt.rn.f16x2.f32 %0, %1, %2;" : "=r"(r) : "f"(hi), "f"(lo));
    return r;
}

// packed silu on fp16x2: h = x * (0.5*tanh(0.5x) + 0.5). ONE MUFU per 2 elems.
__device__ __forceinline__ u32 silu_pk(u32 hx) {
    u32 t, th, s, r;
    asm("mul.f16x2 %0, %1, %2;" : "=r"(t)  : "r"(hx), "r"(HALF2_HALF));
    asm("tanh.approx.f16x2 %0, %1;" : "=r"(th) : "r"(t));
    asm("fma.rn.f16x2 %0, %1, %2, %3;" : "=r"(s) : "r"(th), "r"(HALF2_HALF), "r"(HALF2_HALF));
    asm("mul.f16x2 %0, %1, %2;" : "=r"(r) : "r"(hx), "r"(s));
    return r;
}

// accumulate in place
__device__ __forceinline__ void mma_fp16(float* d, u32 a0, u32 a1, u32 a2, u32 a3,
                                         u32 b0, u32 b1) {
    asm volatile("mma.sync.aligned.m16n8k16.row.col.f32.f16.f16.f32 "
                 "{%0,%1,%2,%3}, {%4,%5,%6,%7}, {%8,%9}, {%0,%1,%2,%3};"
                 : "+f"(d[0]), "+f"(d[1]), "+f"(d[2]), "+f"(d[3])
                 : "r"(a0), "r"(a1), "r"(a2), "r"(a3), "r"(b0), "r"(b1));
}

// first k-step: D (write-only) = A*B + {cx, cy, cx, cy}  (bias via C operand)
__device__ __forceinline__ void mma_fp16_c(float* d, u32 a0, u32 a1, u32 a2, u32 a3,
                                           u32 b0, u32 b1, float cx, float cy) {
    asm volatile("mma.sync.aligned.m16n8k16.row.col.f32.f16.f16.f32 "
                 "{%0,%1,%2,%3}, {%4,%5,%6,%7}, {%8,%9}, {%10,%11,%10,%11};"
                 : "=f"(d[0]), "=f"(d[1]), "=f"(d[2]), "=f"(d[3])
                 : "r"(a0), "r"(a1), "r"(a2), "r"(a3), "r"(b0), "r"(b1),
                   "f"(cx), "f"(cy));
}

__device__ __forceinline__ void ldsm_x4(u32& r0, u32& r1, u32& r2, u32& r3, u32 addr) {
    asm volatile("ldmatrix.sync.aligned.m8n8.x4.shared.b16 {%0,%1,%2,%3}, [%4];"
                 : "=r"(r0), "=r"(r1), "=r"(r2), "=r"(r3) : "r"(addr));
}

// build trig features k=32..47 into trig smem row (tid), return sin(8*pi*rho)
// order: [rho, cos1..cos8, sin1..sin7]
__device__ __forceinline__ float build_trig(char* smem, int tid, float r) {
    float xv[16];
    xv[0] = r;
    float s1, c1;
    sincosf(PI_F * r, &s1, &c1);
    float ck = c1, sk = s1;
    xv[1] = ck; xv[9] = sk;
    float s8 = s1;
    #pragma unroll
    for (int k = 2; k <= N_MODES; k++) {
        float cn = fmaf(ck, c1, -sk * s1);
        float sn = fmaf(sk, c1,  ck * s1);
        ck = cn; sk = sn;
        xv[k] = ck;
        if (k < 8) xv[8 + k] = sk;
        else       s8 = sk;
    }
    uint4 v0 = make_uint4(pk16(xv[0], xv[1]), pk16(xv[2], xv[3]),
                          pk16(xv[4], xv[5]), pk16(xv[6], xv[7]));
    uint4 v1 = make_uint4(pk16(xv[8], xv[9]), pk16(xv[10], xv[11]),
                          pk16(xv[12], xv[13]), pk16(xv[14], xv[15]));
    char* rowp = smem + SM_TRIG + tid * TRIG_STRIDE_B;
    *(uint4*)(rowp)      = v0;
    *(uint4*)(rowp + 16) = v1;
    return s8;
}

__global__ __launch_bounds__(TPB, 4)
void slfm_hmma_kernel(const int* __restrict__ time_idx,
                      const float* __restrict__ rho,
                      const float* __restrict__ emb,
                      const float* __restrict__ W0,
                      const float* __restrict__ b0g,
                      const float* __restrict__ W1,
                      const float* __restrict__ b1g,
                      const float* __restrict__ Woutg,
                      const float* __restrict__ boutg,
                      float* __restrict__ outp,
                      int n, int ntiles)
{
    extern __shared__ char smem[];
    const u32 sb = smem_u32(smem);
    const int tid  = threadIdx.x;
    const int lane = tid & 31;
    const int warp = tid >> 5;
    const int g    = lane >> 2;
    const int t4   = lane & 3;
    const int rowA = warp * 32;

    // ---- stage emb table as fp16: row stride 64B, chunk q stored at q^(row&3) ----
    for (int i = tid; i < (N_TIME - 1) * 4; i += TPB) {
        int row = i >> 2, q = i & 3;
        const float4* e = (const float4*)(emb + row * LATENT) + q * 2;
        float4 e0 = e[0], e1 = e[1];
        uint4 v = make_uint4(pk16(e0.x, e0.y), pk16(e0.z, e0.w),
                             pk16(e1.x, e1.y), pk16(e1.z, e1.w));
        int qs = q ^ (row & 3);   // bank swizzle
        *(uint4*)(smem + SM_EMB + row * EMB_STRIDE_B + qs * 16) = v;
    }

    // ---- stage fp16 weight fragments (hi only) ----
    for (int i = tid; i < 512; i += TPB) {
        int ks = i >> 7, ntp = (i >> 5) & 3, ln = i & 31;
        int gg = ln >> 2, tt = ln & 3;
        int k0 = ks * 16 + tt * 2;

        {   // layer 1, all ks
            u32 hh[4];
            #pragma unroll
            for (int sub = 0; sub < 2; sub++) {
                int nn = (ntp * 2 + sub) * 8 + gg;
                hh[sub*2+0] = pk16(W1[(k0    ) * HIDDEN + nn],
                                   W1[(k0 + 1) * HIDDEN + nn]);
                hh[sub*2+1] = pk16(W1[(k0 + 8) * HIDDEN + nn],
                                   W1[(k0 + 9) * HIDDEN + nn]);
            }
            int off = ((ks * 4 + ntp) * 32 + ln) * 16;
            *(uint4*)(smem + SM_F1H + off) = make_uint4(hh[0], hh[1], hh[2], hh[3]);
        }
        if (ks < 3) {   // layer 0, k = 0..47
            u32 hh[4];
            #pragma unroll
            for (int sub = 0; sub < 2; sub++) {
                int nn = (ntp * 2 + sub) * 8 + gg;
                hh[sub*2+0] = pk16(W0[(k0    ) * HIDDEN + nn],
                                   W0[(k0 + 1) * HIDDEN + nn]);
                hh[sub*2+1] = pk16(W0[(k0 + 8) * HIDDEN + nn],
                                   W0[(k0 + 9) * HIDDEN + nn]);
            }
            int off = ((ks * 4 + ntp) * 32 + ln) * 16;
            *(uint4*)(smem + SM_F0H + off) = make_uint4(hh[0], hh[1], hh[2], hh[3]);
        }
    }
    if (tid < HIDDEN) {
        ((float*)(smem + SM_B0))[tid] = b0g[tid];
        ((float*)(smem + SM_B1))[tid] = b1g[tid];
        ((float*)(smem + SM_WO))[tid] = Woutg[tid];
        ((float*)(smem + SM_W48))[tid] = W0[48 * HIDDEN + tid];
    }
    if (tid == 0) *((float*)(smem + SM_BO)) = boutg[0] + BASE_LOGIT;

    // trig ldmatrix base (static per lane)
    const u32 trigBase = sb + SM_TRIG +
        (u32)((rowA + (lane & 15)) * TRIG_STRIDE_B + (lane >> 4) * 16);
    const int chunkSel = lane >> 4;   // 0 or 1

    // ---- prologue: first tile point data + trig ----
    int tile = blockIdx.x;
    int t_c = 0, idx_c = 0;
    float s8_c = 0.0f;
    if (tile < ntiles) {
        int p = tile * M_TILE + tid;
        int ps = p < n ? p : n - 1;
        t_c = time_idx[ps];
        float r0 = rho[ps];
        idx_c = t_c - 1;
        idx_c = idx_c < 0 ? 0 : (idx_c > N_TIME - 2 ? N_TIME - 2 : idx_c);
        s8_c = build_trig(smem, tid, r0);
    }
    __syncthreads();   // staging + trig visible

    // ---- loop-invariant register state ----
    // Wout B-fragments (replicated-dot trick)
    u32 wb[4][2];
    {
        const float* wo = (const float*)(smem + SM_WO);
        #pragma unroll
        for (int ks = 0; ks < 4; ks++) {
            int k0 = ks * 16 + t4 * 2;
            wb[ks][0] = pk16(wo[k0],     wo[k0 + 1]);
            wb[ks][1] = pk16(wo[k0 + 8], wo[k0 + 9]);
        }
    }
    // bias pairs per n-tile (column-only dependence -> C operand {bx,by,bx,by})
    float2 bias0[8], bias1[8];
    #pragma unroll
    for (int nt = 0; nt < 8; nt++) {
        int n0 = nt * 8 + t4 * 2;
        bias0[nt] = *(const float2*)(smem + SM_B0 + n0 * 4);
        bias1[nt] = *(const float2*)(smem + SM_B1 + n0 * 4);
    }
    const float outb = *((const float*)(smem + SM_BO));  // bout + BASE_LOGIT

    for (; tile < ntiles; tile += GRID_CTAS) {
        // ---------- next-tile LDGs (tiny) ----------
        int ntile2 = tile + GRID_CTAS;
        int   t_n = 0, idx_n = 0;
        float r_n = 0.0f;
        if (ntile2 < ntiles) {
            int p = ntile2 * M_TILE + tid;
            int ps = p < n ? p : n - 1;
            t_n = time_idx[ps];
            r_n = rho[ps];
            idx_n = t_n - 1;
            idx_n = idx_n < 0 ? 0 : (idx_n > N_TIME - 2 ? N_TIME - 2 : idx_n);
        }

        // ---------- layer 0: A from emb table (ks 0,1) + trig (ks 2) ----------
        float d0[2][8][4];

        u32 ah[2][3][4];
        #pragma unroll
        for (int mt = 0; mt < 2; mt++) {
            int idxr = __shfl_sync(0xffffffffu, idx_c, (lane & 15) | (mt << 4));
            u32 rbase = sb + SM_EMB + (u32)idxr * EMB_STRIDE_B;
            int sw = idxr & 3;
            u32 a0 = rbase + (u32)((chunkSel ^ sw) * 16);           // chunks 0,1
            u32 a1 = rbase + (u32)(((chunkSel + 2) ^ sw) * 16);     // chunks 2,3
            ldsm_x4(ah[mt][0][0], ah[mt][0][1], ah[mt][0][2], ah[mt][0][3], a0);
            ldsm_x4(ah[mt][1][0], ah[mt][1][1], ah[mt][1][2], ah[mt][1][3], a1);
            u32 tb = trigBase + (u32)(mt * 16 * TRIG_STRIDE_B);
            ldsm_x4(ah[mt][2][0], ah[mt][2][1], ah[mt][2][2], ah[mt][2][3], tb);
        }

        // ks = 0: bias-in-C (no accumulator init needed)
        #pragma unroll
        for (int ntp = 0; ntp < 4; ntp++) {
            int off = ((0 * 4 + ntp) * 32 + lane) * 16;
            uint4 bh = *(const uint4*)(smem + SM_F0H + off);
            #pragma unroll
            for (int mt = 0; mt < 2; mt++) {
                u32* a = ah[mt][0];
                mma_fp16_c(d0[mt][2*ntp],   a[0], a[1], a[2], a[3], bh.x, bh.y,
                           bias0[2*ntp].x,   bias0[2*ntp].y);
                mma_fp16_c(d0[mt][2*ntp+1], a[0], a[1], a[2], a[3], bh.z, bh.w,
                           bias0[2*ntp+1].x, bias0[2*ntp+1].y);
            }
        }
        // ks = 1, 2: accumulate
        #pragma unroll
        for (int ks = 1; ks < 3; ks++) {
            #pragma unroll
            for (int ntp = 0; ntp < 4; ntp++) {
                int off = ((ks * 4 + ntp) * 32 + lane) * 16;
                uint4 bh = *(const uint4*)(smem + SM_F0H + off);
                #pragma unroll
                for (int mt = 0; mt < 2; mt++) {
                    u32* a = ah[mt][ks];
                    mma_fp16(d0[mt][2*ntp],   a[0], a[1], a[2], a[3], bh.x, bh.y);
                    mma_fp16(d0[mt][2*ntp+1], a[0], a[1], a[2], a[3], bh.z, bh.w);
                }
            }
        }
        __syncwarp();   // warp's trig reads complete -> trig rows dead

        // ---------- rebuild trig for next tile ----------
        float s8_n = 0.0f;
        if (ntile2 < ntiles) s8_n = build_trig(smem, tid, r_n);

        // ---------- k=48 rank-1 fix: d0 += sin(8*pi*rho_row) * W0[48][col] ----------
        #pragma unroll
        for (int mt = 0; mt < 2; mt++) {
            float s8T = __shfl_sync(0xffffffffu, s8_c, mt * 16 + g);
            float s8B = __shfl_sync(0xffffffffu, s8_c, mt * 16 + g + 8);
            #pragma unroll
            for (int nt = 0; nt < 8; nt++) {
                int n0 = nt * 8 + t4 * 2;
                float2 w48 = *(const float2*)(smem + SM_W48 + n0 * 4);
                d0[mt][nt][0] = fmaf(s8T, w48.x, d0[mt][nt][0]);
                d0[mt][nt][1] = fmaf(s8T, w48.y, d0[mt][nt][1]);
                d0[mt][nt][2] = fmaf(s8B, w48.x, d0[mt][nt][2]);
                d0[mt][nt][3] = fmaf(s8B, w48.y, d0[mt][nt][3]);
            }
        }

        // ---------- epilogue 0: pack -> PACKED silu (f16x2) -> layer-1 A frags ----------
        u32 ah1[2][4][4];
        #pragma unroll
        for (int mt = 0; mt < 2; mt++) {
            #pragma unroll
            for (int ks = 0; ks < 4; ks++) {
                ah1[mt][ks][0] = silu_pk(pk16(d0[mt][2*ks][0],   d0[mt][2*ks][1]));
                ah1[mt][ks][1] = silu_pk(pk16(d0[mt][2*ks][2],   d0[mt][2*ks][3]));
                ah1[mt][ks][2] = silu_pk(pk16(d0[mt][2*ks+1][0], d0[mt][2*ks+1][1]));
                ah1[mt][ks][3] = silu_pk(pk16(d0[mt][2*ks+1][2], d0[mt][2*ks+1][3]));
            }
        }

        // ---------- layer 1: ks=0 bias-in-C, ks=1..3 accumulate ----------
        float d1[2][8][4];
        #pragma unroll
        for (int ntp = 0; ntp < 4; ntp++) {
            int off = ((0 * 4 + ntp) * 32 + lane) * 16;
            uint4 bh = *(const uint4*)(smem + SM_F1H + off);
            #pragma unroll
            for (int mt = 0; mt < 2; mt++) {
                u32* a = ah1[mt][0];
                mma_fp16_c(d1[mt][2*ntp],   a[0], a[1], a[2], a[3], bh.x, bh.y,
                           bias1[2*ntp].x,   bias1[2*ntp].y);
                mma_fp16_c(d1[mt][2*ntp+1], a[0], a[1], a[2], a[3], bh.z, bh.w,
                           bias1[2*ntp+1].x, bias1[2*ntp+1].y);
            }
        }
        #pragma unroll
        for (int ks = 1; ks < 4; ks++) {
            #pragma unroll
            for (int ntp = 0; ntp < 4; ntp++) {
                int off = ((ks * 4 + ntp) * 32 + lane) * 16;
                uint4 bh = *(const uint4*)(smem + SM_F1H + off);
                #pragma unroll
                for (int mt = 0; mt < 2; mt++) {
                    u32* a = ah1[mt][ks];
                    mma_fp16(d1[mt][2*ntp],   a[0], a[1], a[2], a[3], bh.x, bh.y);
                    mma_fp16(d1[mt][2*ntp+1], a[0], a[1], a[2], a[3], bh.z, bh.w);
                }
            }
        }

        // ---------- final: PACKED silu -> A frags -> Wout dot ON TENSOR PIPE ----------
        #pragma unroll
        for (int mt = 0; mt < 2; mt++) {
            float dd[4];
            {
                u32 a0 = silu_pk(pk16(d1[mt][0][0], d1[mt][0][1]));
                u32 a1 = silu_pk(pk16(d1[mt][0][2], d1[mt][0][3]));
                u32 a2 = silu_pk(pk16(d1[mt][1][0], d1[mt][1][1]));
                u32 a3 = silu_pk(pk16(d1[mt][1][2], d1[mt][1][3]));
                mma_fp16_c(dd, a0, a1, a2, a3, wb[0][0], wb[0][1], outb, outb);
            }
            #pragma unroll
            for (int ks = 1; ks < 4; ks++) {
                u32 a0 = silu_pk(pk16(d1[mt][2*ks][0],   d1[mt][2*ks][1]));
                u32 a1 = silu_pk(pk16(d1[mt][2*ks][2],   d1[mt][2*ks][3]));
                u32 a2 = silu_pk(pk16(d1[mt][2*ks+1][0], d1[mt][2*ks+1][1]));
                u32 a3 = silu_pk(pk16(d1[mt][2*ks+1][2], d1[mt][2*ks+1][3]));
                mma_fp16(dd, a0, a1, a2, a3, wb[ks][0], wb[ks][1]);
            }
            // dd[0] = raw(row g), dd[2] = raw(row g+8)  (duplicated over t4)
            int rlT = mt * 16 + g;
            int rlB = rlT + 8;
            int tT = __shfl_sync(0xffffffffu, t_c, rlT);
            int tB = __shfl_sync(0xffffffffu, t_c, rlB);
            if (t4 == 0) {
                int pT = tile * M_TILE + rowA + rlT;
                int pB = tile * M_TILE + rowA + rlB;
                float thT = __fdividef(1.0f, 1.0f + __expf(-dd[0]));
                float thB = __fdividef(1.0f, 1.0f + __expf(-dd[2]));
                float oT = (tT == 0) ? (X_A0 * CSANMAX) : thT * CSANMAX;
                float oB = (tB == 0) ? (X_A0 * CSANMAX) : thB * CSANMAX;
                if (pT < n) outp[pT] = oT;
                if (pB < n) outp[pB] = oB;
            }
        }
        __syncwarp();
        t_c = t_n;
        idx_c = idx_n;
        s8_c = s8_n;
    }
}

extern "C" void kernel_launch(void* const* d_in, const int* in_sizes, int n_in,
                              void* d_out, int out_size)
{
    const int*   time_idx = (const int*)  d_in[0];
    const float* rho      = (const float*)d_in[1];
    const float* emb      = (const float*)d_in[2];
    const float* W0       = (const float*)d_in[3];
    const float* b0       = (const float*)d_in[4];
    const float* W1       = (const float*)d_in[5];
    const float* b1       = (const float*)d_in[6];
    const float* Wout     = (const float*)d_in[7];
    const float* bout     = (const float*)d_in[8];
    float* out = (float*)d_out;

    int n = in_sizes[0];
    int ntiles = (n + M_TILE - 1) / M_TILE;

    cudaFuncSetAttribute(slfm_hmma_kernel,
                         cudaFuncAttributeMaxDynamicSharedMemorySize, SM_TOTAL);
    int grid = ntiles < GRID_CTAS ? ntiles : GRID_CTAS;
    slfm_hmma_kernel<<<grid, TPB, SM_TOTAL>>>(time_idx, rho, emb, W0, b0, W1, b1,
                                              Wout, bout, out, n, ntiles);
}

// round 15
// speedup vs baseline: 1.0367x; 1.0367x over previous
#include <cuda_runtime.h>
#include <cuda_fp16.h>
#include <cstdint>
#include <math.h>

#define N_TIME   512
#define LATENT   32
#define HIDDEN   64
#define N_MODES  8
#define X_A0     0.3f
#define CSANMAX  28700.0f
#define BASE_LOGIT (-0.8472978603872034f)
#define PI_F 3.14159265358979323846f

#define TPB       128
#define M_TILE    128
#define GRID_CTAS 592

#define EMB_STRIDE_B  64   // bytes per emb row (32 fp16); 16B-aligned for ldmatrix
#define TRIG_STRIDE_B 48   // bytes per trig row; 16B-aligned, conflict-free

// ---- smem layout (bytes) ----
#define SM_EMB  0                          // 511 * 64 -> pad 32768
#define SM_TRIG 32768                      // 128 * 48 = 6144
#define SM_F0H  (SM_TRIG + 6144)           // 38912, 3ks*4ntp*32*16 = 6144
#define SM_F1H  (SM_F0H + 6144)            // 45056, 4ks -> 8192
#define SM_B0   (SM_F1H + 8192)            // 53248
#define SM_B1   (SM_B0 + 256)
#define SM_WO   (SM_B1 + 256)
#define SM_W48  (SM_WO + 256)              // W0 row 48 (fp32)
#define SM_BO   (SM_W48 + 256)
#define SM_TOTAL (SM_BO + 16)              // 54288 (~53 KB) -> 4 CTAs/SM

typedef uint32_t u32;

#define HALF2_HALF 0x38003800u   // fp16x2 {0.5, 0.5}

__device__ __forceinline__ u32 smem_u32(const void* p) {
    u32 a;
    asm("{ .reg .u64 t; cvta.to.shared.u64 t, %1; cvt.u32.u64 %0, t; }"
        : "=r"(a) : "l"(p));
    return a;
}

// pack two fp32 -> fp16x2, first arg in LOW half
__device__ __forceinline__ u32 pk16(float lo, float hi) {
    u32 r;
    asm("cvt.rn.f16x2.f32 %0, %1, %2;" : "=r"(r) : "f"(hi), "f"(lo));
    return r;
}

// packed silu on fp16x2: h = x * (0.5*tanh(0.5x) + 0.5). ONE MUFU per 2 elems.
__device__ __forceinline__ u32 silu_pk(u32 hx) {
    u32 t, th, s, r;
    asm("mul.f16x2 %0, %1, %2;" : "=r"(t)  : "r"(hx), "r"(HALF2_HALF));
    asm("tanh.approx.f16x2 %0, %1;" : "=r"(th) : "r"(t));
    asm("fma.rn.f16x2 %0, %1, %2, %3;" : "=r"(s) : "r"(th), "r"(HALF2_HALF), "r"(HALF2_HALF));
    asm("mul.f16x2 %0, %1, %2;" : "=r"(r) : "r"(hx), "r"(s));
    return r;
}

// accumulate in place
__device__ __forceinline__ void mma_fp16(float* d, u32 a0, u32 a1, u32 a2, u32 a3,
                                         u32 b0, u32 b1) {
    asm volatile("mma.sync.aligned.m16n8k16.row.col.f32.f16.f16.f32 "
                 "{%0,%1,%2,%3}, {%4,%5,%6,%7}, {%8,%9}, {%0,%1,%2,%3};"
                 : "+f"(d[0]), "+f"(d[1]), "+f"(d[2]), "+f"(d[3])
                 : "r"(a0), "r"(a1), "r"(a2), "r"(a3), "r"(b0), "r"(b1));
}

// first k-step: D (write-only) = A*B + {cx, cy, cx, cy}  (bias via C operand)
__device__ __forceinline__ void mma_fp16_c(float* d, u32 a0, u32 a1, u32 a2, u32 a3,
                                           u32 b0, u32 b1, float cx, float cy) {
    asm volatile("mma.sync.aligned.m16n8k16.row.col.f32.f16.f16.f32 "
                 "{%0,%1,%2,%3}, {%4,%5,%6,%7}, {%8,%9}, {%10,%11,%10,%11};"
                 : "=f"(d[0]), "=f"(d[1]), "=f"(d[2]), "=f"(d[3])
                 : "r"(a0), "r"(a1), "r"(a2), "r"(a3), "r"(b0), "r"(b1),
                   "f"(cx), "f"(cy));
}

__device__ __forceinline__ void ldsm_x4(u32& r0, u32& r1, u32& r2, u32& r3, u32 addr) {
    asm volatile("ldmatrix.sync.aligned.m8n8.x4.shared.b16 {%0,%1,%2,%3}, [%4];"
                 : "=r"(r0), "=r"(r1), "=r"(r2), "=r"(r3) : "r"(addr));
}

// build trig features k=32..47 into trig smem row (tid), return sin(8*pi*rho)
// order: [rho, cos1..cos8, sin1..sin7]
__device__ __forceinline__ float build_trig(char* smem, int tid, float r) {
    float xv[16];
    xv[0] = r;
    float s1, c1;
    sincosf(PI_F * r, &s1, &c1);
    float ck = c1, sk = s1;
    xv[1] = ck; xv[9] = sk;
    float s8 = s1;
    #pragma unroll
    for (int k = 2; k <= N_MODES; k++) {
        float cn = fmaf(ck, c1, -sk * s1);
        float sn = fmaf(sk, c1,  ck * s1);
        ck = cn; sk = sn;
        xv[k] = ck;
        if (k < 8) xv[8 + k] = sk;
        else       s8 = sk;
    }
    uint4 v0 = make_uint4(pk16(xv[0], xv[1]), pk16(xv[2], xv[3]),
                          pk16(xv[4], xv[5]), pk16(xv[6], xv[7]));
    uint4 v1 = make_uint4(pk16(xv[8], xv[9]), pk16(xv[10], xv[11]),
                          pk16(xv[12], xv[13]), pk16(xv[14], xv[15]));
    char* rowp = smem + SM_TRIG + tid * TRIG_STRIDE_B;
    *(uint4*)(rowp)      = v0;
    *(uint4*)(rowp + 16) = v1;
    return s8;
}

__global__ __launch_bounds__(TPB, 4)
void slfm_hmma_kernel(const int* __restrict__ time_idx,
                      const float* __restrict__ rho,
                      const float* __restrict__ emb,
                      const float* __restrict__ W0,
                      const float* __restrict__ b0g,
                      const float* __restrict__ W1,
                      const float* __restrict__ b1g,
                      const float* __restrict__ Woutg,
                      const float* __restrict__ boutg,
                      float* __restrict__ outp,
                      int n, int ntiles)
{
    extern __shared__ char smem[];
    const u32 sb = smem_u32(smem);
    const int tid  = threadIdx.x;
    const int lane = tid & 31;
    const int warp = tid >> 5;
    const int g    = lane >> 2;
    const int t4   = lane & 3;
    const int rowA = warp * 32;

    // ---- stage emb table as fp16: row stride 64B, chunk q stored at q^(row&3) ----
    for (int i = tid; i < (N_TIME - 1) * 4; i += TPB) {
        int row = i >> 2, q = i & 3;
        const float4* e = (const float4*)(emb + row * LATENT) + q * 2;
        float4 e0 = e[0], e1 = e[1];
        uint4 v = make_uint4(pk16(e0.x, e0.y), pk16(e0.z, e0.w),
                             pk16(e1.x, e1.y), pk16(e1.z, e1.w));
        int qs = q ^ (row & 3);   // bank swizzle
        *(uint4*)(smem + SM_EMB + row * EMB_STRIDE_B + qs * 16) = v;
    }

    // ---- stage fp16 weight fragments (hi only) ----
    for (int i = tid; i < 512; i += TPB) {
        int ks = i >> 7, ntp = (i >> 5) & 3, ln = i & 31;
        int gg = ln >> 2, tt = ln & 3;
        int k0 = ks * 16 + tt * 2;

        {   // layer 1, all ks
            u32 hh[4];
            #pragma unroll
            for (int sub = 0; sub < 2; sub++) {
                int nn = (ntp * 2 + sub) * 8 + gg;
                hh[sub*2+0] = pk16(W1[(k0    ) * HIDDEN + nn],
                                   W1[(k0 + 1) * HIDDEN + nn]);
                hh[sub*2+1] = pk16(W1[(k0 + 8) * HIDDEN + nn],
                                   W1[(k0 + 9) * HIDDEN + nn]);
            }
            int off = ((ks * 4 + ntp) * 32 + ln) * 16;
            *(uint4*)(smem + SM_F1H + off) = make_uint4(hh[0], hh[1], hh[2], hh[3]);
        }
        if (ks < 3) {   // layer 0, k = 0..47
            u32 hh[4];
            #pragma unroll
            for (int sub = 0; sub < 2; sub++) {
                int nn = (ntp * 2 + sub) * 8 + gg;
                hh[sub*2+0] = pk16(W0[(k0    ) * HIDDEN + nn],
                                   W0[(k0 + 1) * HIDDEN + nn]);
                hh[sub*2+1] = pk16(W0[(k0 + 8) * HIDDEN + nn],
                                   W0[(k0 + 9) * HIDDEN + nn]);
            }
            int off = ((ks * 4 + ntp) * 32 + ln) * 16;
            *(uint4*)(smem + SM_F0H + off) = make_uint4(hh[0], hh[1], hh[2], hh[3]);
        }
    }
    if (tid < HIDDEN) {
        ((float*)(smem + SM_B0))[tid] = b0g[tid];
        ((float*)(smem + SM_B1))[tid] = b1g[tid];
        ((float*)(smem + SM_WO))[tid] = Woutg[tid];
        ((float*)(smem + SM_W48))[tid] = W0[48 * HIDDEN + tid];
    }
    if (tid == 0) *((float*)(smem + SM_BO)) = boutg[0] + BASE_LOGIT;

    // trig ldmatrix base (static per lane)
    const u32 trigBase = sb + SM_TRIG +
        (u32)((rowA + (lane & 15)) * TRIG_STRIDE_B + (lane >> 4) * 16);
    const int chunkSel = lane >> 4;   // 0 or 1

    // ---- prologue: first tile point data + trig ----
    int tile = blockIdx.x;
    int t_c = 0, idx_c = 0;
    float s8_c = 0.0f;
    if (tile < ntiles) {
        int p = tile * M_TILE + tid;
        int ps = p < n ? p : n - 1;
        t_c = time_idx[ps];
        float r0 = rho[ps];
        idx_c = t_c - 1;
        idx_c = idx_c < 0 ? 0 : (idx_c > N_TIME - 2 ? N_TIME - 2 : idx_c);
        s8_c = build_trig(smem, tid, r0);
    }
    __syncthreads();   // staging + trig visible

    // ---- loop-invariant Wout B-fragments (replicated-dot trick) ----
    u32 wb[4][2];
    {
        const float* wo = (const float*)(smem + SM_WO);
        #pragma unroll
        for (int ks = 0; ks < 4; ks++) {
            int k0 = ks * 16 + t4 * 2;
            wb[ks][0] = pk16(wo[k0],     wo[k0 + 1]);
            wb[ks][1] = pk16(wo[k0 + 8], wo[k0 + 9]);
        }
    }
    const float outb = *((const float*)(smem + SM_BO));  // bout + BASE_LOGIT
    const u32 biasB0 = sb + SM_B0 + (u32)(t4 * 8);       // per-lane bias base (t4*2 floats)
    const u32 biasB1 = sb + SM_B1 + (u32)(t4 * 8);

    for (; tile < ntiles; tile += GRID_CTAS) {
        // ---------- next-tile LDGs (tiny) ----------
        int ntile2 = tile + GRID_CTAS;
        int   t_n = 0, idx_n = 0;
        float r_n = 0.0f;
        if (ntile2 < ntiles) {
            int p = ntile2 * M_TILE + tid;
            int ps = p < n ? p : n - 1;
            t_n = time_idx[ps];
            r_n = rho[ps];
            idx_n = t_n - 1;
            idx_n = idx_n < 0 ? 0 : (idx_n > N_TIME - 2 ? N_TIME - 2 : idx_n);
        }

        // ---------- layer 0: A from emb table (ks 0,1) + trig (ks 2) ----------
        float d0[2][8][4];

        u32 ah[2][3][4];
        #pragma unroll
        for (int mt = 0; mt < 2; mt++) {
            int idxr = __shfl_sync(0xffffffffu, idx_c, (lane & 15) | (mt << 4));
            u32 rbase = sb + SM_EMB + (u32)idxr * EMB_STRIDE_B;
            int sw = idxr & 3;
            u32 a0 = rbase + (u32)((chunkSel ^ sw) * 16);           // chunks 0,1
            u32 a1 = rbase + (u32)(((chunkSel + 2) ^ sw) * 16);     // chunks 2,3
            ldsm_x4(ah[mt][0][0], ah[mt][0][1], ah[mt][0][2], ah[mt][0][3], a0);
            ldsm_x4(ah[mt][1][0], ah[mt][1][1], ah[mt][1][2], ah[mt][1][3], a1);
            u32 tb = trigBase + (u32)(mt * 16 * TRIG_STRIDE_B);
            ldsm_x4(ah[mt][2][0], ah[mt][2][1], ah[mt][2][2], ah[mt][2][3], tb);
        }

        // ks = 0: bias-in-C, bias pair loaded JUST-IN-TIME (transient regs)
        #pragma unroll
        for (int ntp = 0; ntp < 4; ntp++) {
            int off = ((0 * 4 + ntp) * 32 + lane) * 16;
            uint4 bh = *(const uint4*)(smem + SM_F0H + off);
            float2 bbA, bbB;
            asm("ld.shared.v2.f32 {%0, %1}, [%2];"
                : "=f"(bbA.x), "=f"(bbA.y) : "r"(biasB0 + (u32)(ntp * 64)));
            asm("ld.shared.v2.f32 {%0, %1}, [%2];"
                : "=f"(bbB.x), "=f"(bbB.y) : "r"(biasB0 + (u32)(ntp * 64 + 32)));
            #pragma unroll
            for (int mt = 0; mt < 2; mt++) {
                u32* a = ah[mt][0];
                mma_fp16_c(d0[mt][2*ntp],   a[0], a[1], a[2], a[3], bh.x, bh.y,
                           bbA.x, bbA.y);
                mma_fp16_c(d0[mt][2*ntp+1], a[0], a[1], a[2], a[3], bh.z, bh.w,
                           bbB.x, bbB.y);
            }
        }
        // ks = 1, 2: accumulate
        #pragma unroll
        for (int ks = 1; ks < 3; ks++) {
            #pragma unroll
            for (int ntp = 0; ntp < 4; ntp++) {
                int off = ((ks * 4 + ntp) * 32 + lane) * 16;
                uint4 bh = *(const uint4*)(smem + SM_F0H + off);
                #pragma unroll
                for (int mt = 0; mt < 2; mt++) {
                    u32* a = ah[mt][ks];
                    mma_fp16(d0[mt][2*ntp],   a[0], a[1], a[2], a[3], bh.x, bh.y);
                    mma_fp16(d0[mt][2*ntp+1], a[0], a[1], a[2], a[3], bh.z, bh.w);
                }
            }
        }
        __syncwarp();   // warp's trig reads complete -> trig rows dead

        // ---------- rebuild trig for next tile ----------
        float s8_n = 0.0f;
        if (ntile2 < ntiles) s8_n = build_trig(smem, tid, r_n);

        // ---------- k=48 rank-1 fix: d0 += sin(8*pi*rho_row) * W0[48][col] ----------
        #pragma unroll
        for (int mt = 0; mt < 2; mt++) {
            float s8T = __shfl_sync(0xffffffffu, s8_c, mt * 16 + g);
            float s8B = __shfl_sync(0xffffffffu, s8_c, mt * 16 + g + 8);
            #pragma unroll
            for (int nt = 0; nt < 8; nt++) {
                int n0 = nt * 8 + t4 * 2;
                float2 w48 = *(const float2*)(smem + SM_W48 + n0 * 4);
                d0[mt][nt][0] = fmaf(s8T, w48.x, d0[mt][nt][0]);
                d0[mt][nt][1] = fmaf(s8T, w48.y, d0[mt][nt][1]);
                d0[mt][nt][2] = fmaf(s8B, w48.x, d0[mt][nt][2]);
                d0[mt][nt][3] = fmaf(s8B, w48.y, d0[mt][nt][3]);
            }
        }

        // ---------- epilogue 0: pack -> PACKED silu (f16x2) -> layer-1 A frags ----------
        u32 ah1[2][4][4];
        #pragma unroll
        for (int mt = 0; mt < 2; mt++) {
            #pragma unroll
            for (int ks = 0; ks < 4; ks++) {
                ah1[mt][ks][0] = silu_pk(pk16(d0[mt][2*ks][0],   d0[mt][2*ks][1]));
                ah1[mt][ks][1] = silu_pk(pk16(d0[mt][2*ks][2],   d0[mt][2*ks][3]));
                ah1[mt][ks][2] = silu_pk(pk16(d0[mt][2*ks+1][0], d0[mt][2*ks+1][1]));
                ah1[mt][ks][3] = silu_pk(pk16(d0[mt][2*ks+1][2], d0[mt][2*ks+1][3]));
            }
        }

        // ---------- layer 1: ks=0 bias-in-C (JIT bias load), ks=1..3 accumulate ----------
        float d1[2][8][4];
        #pragma unroll
        for (int ntp = 0; ntp < 4; ntp++) {
            int off = ((0 * 4 + ntp) * 32 + lane) * 16;
            uint4 bh = *(const uint4*)(smem + SM_F1H + off);
            float2 bbA, bbB;
            asm("ld.shared.v2.f32 {%0, %1}, [%2];"
                : "=f"(bbA.x), "=f"(bbA.y) : "r"(biasB1 + (u32)(ntp * 64)));
            asm("ld.shared.v2.f32 {%0, %1}, [%2];"
                : "=f"(bbB.x), "=f"(bbB.y) : "r"(biasB1 + (u32)(ntp * 64 + 32)));
            #pragma unroll
            for (int mt = 0; mt < 2; mt++) {
                u32* a = ah1[mt][0];
                mma_fp16_c(d1[mt][2*ntp],   a[0], a[1], a[2], a[3], bh.x, bh.y,
                           bbA.x, bbA.y);
                mma_fp16_c(d1[mt][2*ntp+1], a[0], a[1], a[2], a[3], bh.z, bh.w,
                           bbB.x, bbB.y);
            }
        }
        #pragma unroll
        for (int ks = 1; ks < 4; ks++) {
            #pragma unroll
            for (int ntp = 0; ntp < 4; ntp++) {
                int off = ((ks * 4 + ntp) * 32 + lane) * 16;
                uint4 bh = *(const uint4*)(smem + SM_F1H + off);
                #pragma unroll
                for (int mt = 0; mt < 2; mt++) {
                    u32* a = ah1[mt][ks];
                    mma_fp16(d1[mt][2*ntp],   a[0], a[1], a[2], a[3], bh.x, bh.y);
                    mma_fp16(d1[mt][2*ntp+1], a[0], a[1], a[2], a[3], bh.z, bh.w);
                }
            }
        }

        // ---------- final: PACKED silu -> A frags -> Wout dot ON TENSOR PIPE ----------
        #pragma unroll
        for (int mt = 0; mt < 2; mt++) {
            float dd[4];
            {
                u32 a0 = silu_pk(pk16(d1[mt][0][0], d1[mt][0][1]));
                u32 a1 = silu_pk(pk16(d1[mt][0][2], d1[mt][0][3]));
                u32 a2 = silu_pk(pk16(d1[mt][1][0], d1[mt][1][1]));
                u32 a3 = silu_pk(pk16(d1[mt][1][2], d1[mt][1][3]));
                mma_fp16_c(dd, a0, a1, a2, a3, wb[0][0], wb[0][1], outb, outb);
            }
            #pragma unroll
            for (int ks = 1; ks < 4; ks++) {
                u32 a0 = silu_pk(pk16(d1[mt][2*ks][0],   d1[mt][2*ks][1]));
                u32 a1 = silu_pk(pk16(d1[mt][2*ks][2],   d1[mt][2*ks][3]));
                u32 a2 = silu_pk(pk16(d1[mt][2*ks+1][0], d1[mt][2*ks+1][1]));
                u32 a3 = silu_pk(pk16(d1[mt][2*ks+1][2], d1[mt][2*ks+1][3]));
                mma_fp16(dd, a0, a1, a2, a3, wb[ks][0], wb[ks][1]);
            }
            // dd[0] = raw(row g), dd[2] = raw(row g+8)  (duplicated over t4)
            int rlT = mt * 16 + g;
            int rlB = rlT + 8;
            int tT = __shfl_sync(0xffffffffu, t_c, rlT);
            int tB = __shfl_sync(0xffffffffu, t_c, rlB);
            if (t4 == 0) {
                int pT = tile * M_TILE + rowA + rlT;
                int pB = tile * M_TILE + rowA + rlB;
                float thT = __fdividef(1.0f, 1.0f + __expf(-dd[0]));
                float thB = __fdividef(1.0f, 1.0f + __expf(-dd[2]));
                float oT = (tT == 0) ? (X_A0 * CSANMAX) : thT * CSANMAX;
                float oB = (tB == 0) ? (X_A0 * CSANMAX) : thB * CSANMAX;
                if (pT < n) outp[pT] = oT;
                if (pB < n) outp[pB] = oB;
            }
        }
        __syncwarp();
        t_c = t_n;
        idx_c = idx_n;
        s8_c = s8_n;
    }
}

extern "C" void kernel_launch(void* const* d_in, const int* in_sizes, int n_in,
                              void* d_out, int out_size)
{
    const int*   time_idx = (const int*)  d_in[0];
    const float* rho      = (const float*)d_in[1];
    const float* emb      = (const float*)d_in[2];
    const float* W0       = (const float*)d_in[3];
    const float* b0       = (const float*)d_in[4];
    const float* W1       = (const float*)d_in[5];
    const float* b1       = (const float*)d_in[6];
    const float* Wout     = (const float*)d_in[7];
    const float* bout     = (const float*)d_in[8];
    float* out = (float*)d_out;

    int n = in_sizes[0];
    int ntiles = (n + M_TILE - 1) / M_TILE;

    cudaFuncSetAttribute(slfm_hmma_kernel,
                         cudaFuncAttributeMaxDynamicSharedMemorySize, SM_TOTAL);
    int grid = ntiles < GRID_CTAS ? ntiles : GRID_CTAS;
    slfm_hmma_kernel<<<grid, TPB, SM_TOTAL>>>(time_idx, rho, emb, W0, b0, W1, b1,
                                              Wout, bout, out, n, ntiles);
}

// round 16
// speedup vs baseline: 1.0490x; 1.0118x over previous
#include <cuda_runtime.h>
#include <cuda_fp16.h>
#include <cstdint>
#include <math.h>

#define N_TIME   512
#define LATENT   32
#define HIDDEN   64
#define N_MODES  8
#define X_A0     0.3f
#define CSANMAX  28700.0f
#define BASE_LOGIT (-0.8472978603872034f)
#define PI_F 3.14159265358979323846f

#define TPB       128
#define M_TILE    128
#define GRID_CTAS 444

#define EMB_STRIDE_B  64   // bytes per emb row (32 fp16); 16B-aligned for ldmatrix
#define TRIG_STRIDE_B 48   // bytes per trig row; 16B-aligned, conflict-free

// ---- smem layout (bytes) ----
#define SM_EMB  0                          // 511 * 64 -> pad 32768
#define SM_TRIG 32768                      // 128 * 48 = 6144
#define SM_F0H  (SM_TRIG + 6144)           // 38912, 3ks*4ntp*32*16 = 6144
#define SM_F1H  (SM_F0H + 6144)            // 45056, 4ks -> 8192
#define SM_B0   (SM_F1H + 8192)            // 53248
#define SM_B1   (SM_B0 + 256)
#define SM_WO   (SM_B1 + 256)
#define SM_W48  (SM_WO + 256)              // W0 row 48 (fp32)
#define SM_BO   (SM_W48 + 256)
#define SM_TOTAL (SM_BO + 16)              // 54288 (~53 KB)

typedef uint32_t u32;

#define HALF2_HALF 0x38003800u   // fp16x2 {0.5, 0.5}

__device__ __forceinline__ u32 smem_u32(const void* p) {
    u32 a;
    asm("{ .reg .u64 t; cvta.to.shared.u64 t, %1; cvt.u32.u64 %0, t; }"
        : "=r"(a) : "l"(p));
    return a;
}

// pack two fp32 -> fp16x2, first arg in LOW half
__device__ __forceinline__ u32 pk16(float lo, float hi) {
    u32 r;
    asm("cvt.rn.f16x2.f32 %0, %1, %2;" : "=r"(r) : "f"(hi), "f"(lo));
    return r;
}

// packed silu on fp16x2: h = x * (0.5*tanh(0.5x) + 0.5). ONE MUFU per 2 elems.
__device__ __forceinline__ u32 silu_pk(u32 hx) {
    u32 t, th, s, r;
    asm("mul.f16x2 %0, %1, %2;" : "=r"(t)  : "r"(hx), "r"(HALF2_HALF));
    asm("tanh.approx.f16x2 %0, %1;" : "=r"(th) : "r"(t));
    asm("fma.rn.f16x2 %0, %1, %2, %3;" : "=r"(s) : "r"(th), "r"(HALF2_HALF), "r"(HALF2_HALF));
    asm("mul.f16x2 %0, %1, %2;" : "=r"(r) : "r"(hx), "r"(s));
    return r;
}

// accumulate in place
__device__ __forceinline__ void mma_fp16(float* d, u32 a0, u32 a1, u32 a2, u32 a3,
                                         u32 b0, u32 b1) {
    asm volatile("mma.sync.aligned.m16n8k16.row.col.f32.f16.f16.f32 "
                 "{%0,%1,%2,%3}, {%4,%5,%6,%7}, {%8,%9}, {%0,%1,%2,%3};"
                 : "+f"(d[0]), "+f"(d[1]), "+f"(d[2]), "+f"(d[3])
                 : "r"(a0), "r"(a1), "r"(a2), "r"(a3), "r"(b0), "r"(b1));
}

// first k-step: D (write-only) = A*B + {cx, cy, cx, cy}  (bias via C operand)
__device__ __forceinline__ void mma_fp16_c(float* d, u32 a0, u32 a1, u32 a2, u32 a3,
                                           u32 b0, u32 b1, float cx, float cy) {
    asm volatile("mma.sync.aligned.m16n8k16.row.col.f32.f16.f16.f32 "
                 "{%0,%1,%2,%3}, {%4,%5,%6,%7}, {%8,%9}, {%10,%11,%10,%11};"
                 : "=f"(d[0]), "=f"(d[1]), "=f"(d[2]), "=f"(d[3])
                 : "r"(a0), "r"(a1), "r"(a2), "r"(a3), "r"(b0), "r"(b1),
                   "f"(cx), "f"(cy));
}

__device__ __forceinline__ void ldsm_x4(u32& r0, u32& r1, u32& r2, u32& r3, u32 addr) {
    asm volatile("ldmatrix.sync.aligned.m8n8.x4.shared.b16 {%0,%1,%2,%3}, [%4];"
                 : "=r"(r0), "=r"(r1), "=r"(r2), "=r"(r3) : "r"(addr));
}

// build trig features k=32..47 into trig smem row (tid), return sin(8*pi*rho)
// order: [rho, cos1..cos8, sin1..sin7]
__device__ __forceinline__ float build_trig(char* smem, int tid, float r) {
    float xv[16];
    xv[0] = r;
    float s1, c1;
    sincosf(PI_F * r, &s1, &c1);
    float ck = c1, sk = s1;
    xv[1] = ck; xv[9] = sk;
    float s8 = s1;
    #pragma unroll
    for (int k = 2; k <= N_MODES; k++) {
        float cn = fmaf(ck, c1, -sk * s1);
        float sn = fmaf(sk, c1,  ck * s1);
        ck = cn; sk = sn;
        xv[k] = ck;
        if (k < 8) xv[8 + k] = sk;
        else       s8 = sk;
    }
    uint4 v0 = make_uint4(pk16(xv[0], xv[1]), pk16(xv[2], xv[3]),
                          pk16(xv[4], xv[5]), pk16(xv[6], xv[7]));
    uint4 v1 = make_uint4(pk16(xv[8], xv[9]), pk16(xv[10], xv[11]),
                          pk16(xv[12], xv[13]), pk16(xv[14], xv[15]));
    char* rowp = smem + SM_TRIG + tid * TRIG_STRIDE_B;
    *(uint4*)(rowp)      = v0;
    *(uint4*)(rowp + 16) = v1;
    return s8;
}

__global__ __launch_bounds__(TPB, 3)
void slfm_hmma_kernel(const int* __restrict__ time_idx,
                      const float* __restrict__ rho,
                      const float* __restrict__ emb,
                      const float* __restrict__ W0,
                      const float* __restrict__ b0g,
                      const float* __restrict__ W1,
                      const float* __restrict__ b1g,
                      const float* __restrict__ Woutg,
                      const float* __restrict__ boutg,
                      float* __restrict__ outp,
                      int n, int ntiles)
{
    extern __shared__ char smem[];
    const u32 sb = smem_u32(smem);
    const int tid  = threadIdx.x;
    const int lane = tid & 31;
    const int warp = tid >> 5;
    const int g    = lane >> 2;
    const int t4   = lane & 3;
    const int rowA = warp * 32;

    // ---- stage emb table as fp16: row stride 64B, chunk q stored at q^(row&3) ----
    for (int i = tid; i < (N_TIME - 1) * 4; i += TPB) {
        int row = i >> 2, q = i & 3;
        const float4* e = (const float4*)(emb + row * LATENT) + q * 2;
        float4 e0 = e[0], e1 = e[1];
        uint4 v = make_uint4(pk16(e0.x, e0.y), pk16(e0.z, e0.w),
                             pk16(e1.x, e1.y), pk16(e1.z, e1.w));
        int qs = q ^ (row & 3);   // bank swizzle
        *(uint4*)(smem + SM_EMB + row * EMB_STRIDE_B + qs * 16) = v;
    }

    // ---- stage fp16 weight fragments (hi only) ----
    for (int i = tid; i < 512; i += TPB) {
        int ks = i >> 7, ntp = (i >> 5) & 3, ln = i & 31;
        int gg = ln >> 2, tt = ln & 3;
        int k0 = ks * 16 + tt * 2;

        {   // layer 1, all ks
            u32 hh[4];
            #pragma unroll
            for (int sub = 0; sub < 2; sub++) {
                int nn = (ntp * 2 + sub) * 8 + gg;
                hh[sub*2+0] = pk16(W1[(k0    ) * HIDDEN + nn],
                                   W1[(k0 + 1) * HIDDEN + nn]);
                hh[sub*2+1] = pk16(W1[(k0 + 8) * HIDDEN + nn],
                                   W1[(k0 + 9) * HIDDEN + nn]);
            }
            int off = ((ks * 4 + ntp) * 32 + ln) * 16;
            *(uint4*)(smem + SM_F1H + off) = make_uint4(hh[0], hh[1], hh[2], hh[3]);
        }
        if (ks < 3) {   // layer 0, k = 0..47
            u32 hh[4];
            #pragma unroll
            for (int sub = 0; sub < 2; sub++) {
                int nn = (ntp * 2 + sub) * 8 + gg;
                hh[sub*2+0] = pk16(W0[(k0    ) * HIDDEN + nn],
                                   W0[(k0 + 1) * HIDDEN + nn]);
                hh[sub*2+1] = pk16(W0[(k0 + 8) * HIDDEN + nn],
                                   W0[(k0 + 9) * HIDDEN + nn]);
            }
            int off = ((ks * 4 + ntp) * 32 + ln) * 16;
            *(uint4*)(smem + SM_F0H + off) = make_uint4(hh[0], hh[1], hh[2], hh[3]);
        }
    }
    if (tid < HIDDEN) {
        ((float*)(smem + SM_B0))[tid] = b0g[tid];
        ((float*)(smem + SM_B1))[tid] = b1g[tid];
        ((float*)(smem + SM_WO))[tid] = Woutg[tid];
        ((float*)(smem + SM_W48))[tid] = W0[48 * HIDDEN + tid];
    }
    if (tid == 0) *((float*)(smem + SM_BO)) = boutg[0] + BASE_LOGIT;

    // trig ldmatrix base (static per lane)
    const u32 trigBase = sb + SM_TRIG +
        (u32)((rowA + (lane & 15)) * TRIG_STRIDE_B + (lane >> 4) * 16);
    const int chunkSel = lane >> 4;   // 0 or 1

    // ---- prologue: first tile data + trig + A-fragments (pipelined state) ----
    int tile = blockIdx.x;
    int t_c = 0;
    float s8_c = 0.0f;
    u32 ah[2][3][4];   // current tile's A fragments (register resident)
    {
        int p = tile * M_TILE + tid;
        int ps = p < n ? p : n - 1;
        t_c = time_idx[ps];
        float r0 = rho[ps];
        int idx0 = t_c - 1;
        idx0 = idx0 < 0 ? 0 : (idx0 > N_TIME - 2 ? N_TIME - 2 : idx0);
        s8_c = build_trig(smem, tid, r0);
        __syncthreads();   // staging + trig visible
        #pragma unroll
        for (int mt = 0; mt < 2; mt++) {
            int idxr = __shfl_sync(0xffffffffu, idx0, (lane & 15) | (mt << 4));
            u32 rbase = sb + SM_EMB + (u32)idxr * EMB_STRIDE_B;
            int sw = idxr & 3;
            ldsm_x4(ah[mt][0][0], ah[mt][0][1], ah[mt][0][2], ah[mt][0][3],
                    rbase + (u32)((chunkSel ^ sw) * 16));
            ldsm_x4(ah[mt][1][0], ah[mt][1][1], ah[mt][1][2], ah[mt][1][3],
                    rbase + (u32)(((chunkSel + 2) ^ sw) * 16));
            ldsm_x4(ah[mt][2][0], ah[mt][2][1], ah[mt][2][2], ah[mt][2][3],
                    trigBase + (u32)(mt * 16 * TRIG_STRIDE_B));
        }
    }
    __syncwarp();   // warp's trig reads complete -> trig region free

    // ---- loop-invariant Wout B-fragments (replicated-dot trick) ----
    u32 wb[4][2];
    {
        const float* wo = (const float*)(smem + SM_WO);
        #pragma unroll
        for (int ks = 0; ks < 4; ks++) {
            int k0 = ks * 16 + t4 * 2;
            wb[ks][0] = pk16(wo[k0],     wo[k0 + 1]);
            wb[ks][1] = pk16(wo[k0 + 8], wo[k0 + 9]);
        }
    }
    const float outb = *((const float*)(smem + SM_BO));  // bout + BASE_LOGIT
    const u32 biasB0 = sb + SM_B0 + (u32)(t4 * 8);
    const u32 biasB1 = sb + SM_B1 + (u32)(t4 * 8);

    for (; tile < ntiles; tile += GRID_CTAS) {
        // ---------- next-tile LDGs ----------
        int ntile2 = tile + GRID_CTAS;
        bool hasNext = (ntile2 < ntiles);
        int   t_n = 0, idx_n = 0;
        float r_n = 0.0f;
        if (hasNext) {
            int p = ntile2 * M_TILE + tid;
            int ps = p < n ? p : n - 1;
            t_n = time_idx[ps];
            r_n = rho[ps];
            idx_n = t_n - 1;
            idx_n = idx_n < 0 ? 0 : (idx_n > N_TIME - 2 ? N_TIME - 2 : idx_n);
        }

        // ---------- layer 0: A fragments already in registers ----------
        float d0[2][8][4];
        // ks = 0: bias-in-C (JIT bias load, transient regs)
        #pragma unroll
        for (int ntp = 0; ntp < 4; ntp++) {
            int off = ((0 * 4 + ntp) * 32 + lane) * 16;
            uint4 bh = *(const uint4*)(smem + SM_F0H + off);
            float2 bbA, bbB;
            asm("ld.shared.v2.f32 {%0, %1}, [%2];"
                : "=f"(bbA.x), "=f"(bbA.y) : "r"(biasB0 + (u32)(ntp * 64)));
            asm("ld.shared.v2.f32 {%0, %1}, [%2];"
                : "=f"(bbB.x), "=f"(bbB.y) : "r"(biasB0 + (u32)(ntp * 64 + 32)));
            #pragma unroll
            for (int mt = 0; mt < 2; mt++) {
                u32* a = ah[mt][0];
                mma_fp16_c(d0[mt][2*ntp],   a[0], a[1], a[2], a[3], bh.x, bh.y,
                           bbA.x, bbA.y);
                mma_fp16_c(d0[mt][2*ntp+1], a[0], a[1], a[2], a[3], bh.z, bh.w,
                           bbB.x, bbB.y);
            }
        }
        // ks = 1, 2: accumulate
        #pragma unroll
        for (int ks = 1; ks < 3; ks++) {
            #pragma unroll
            for (int ntp = 0; ntp < 4; ntp++) {
                int off = ((ks * 4 + ntp) * 32 + lane) * 16;
                uint4 bh = *(const uint4*)(smem + SM_F0H + off);
                #pragma unroll
                for (int mt = 0; mt < 2; mt++) {
                    u32* a = ah[mt][ks];
                    mma_fp16(d0[mt][2*ntp],   a[0], a[1], a[2], a[3], bh.x, bh.y);
                    mma_fp16(d0[mt][2*ntp+1], a[0], a[1], a[2], a[3], bh.z, bh.w);
                }
            }
        }

        // ---------- k=48 rank-1 fix ----------
        #pragma unroll
        for (int mt = 0; mt < 2; mt++) {
            float s8T = __shfl_sync(0xffffffffu, s8_c, mt * 16 + g);
            float s8B = __shfl_sync(0xffffffffu, s8_c, mt * 16 + g + 8);
            #pragma unroll
            for (int nt = 0; nt < 8; nt++) {
                int n0 = nt * 8 + t4 * 2;
                float2 w48 = *(const float2*)(smem + SM_W48 + n0 * 4);
                d0[mt][nt][0] = fmaf(s8T, w48.x, d0[mt][nt][0]);
                d0[mt][nt][1] = fmaf(s8T, w48.y, d0[mt][nt][1]);
                d0[mt][nt][2] = fmaf(s8B, w48.x, d0[mt][nt][2]);
                d0[mt][nt][3] = fmaf(s8B, w48.y, d0[mt][nt][3]);
            }
        }

        // ---------- epilogue 0: packed silu -> layer-1 A frags (d0 dies) ----------
        u32 ah1[2][4][4];
        #pragma unroll
        for (int mt = 0; mt < 2; mt++) {
            #pragma unroll
            for (int ks = 0; ks < 4; ks++) {
                ah1[mt][ks][0] = silu_pk(pk16(d0[mt][2*ks][0],   d0[mt][2*ks][1]));
                ah1[mt][ks][1] = silu_pk(pk16(d0[mt][2*ks][2],   d0[mt][2*ks][3]));
                ah1[mt][ks][2] = silu_pk(pk16(d0[mt][2*ks+1][0], d0[mt][2*ks+1][1]));
                ah1[mt][ks][3] = silu_pk(pk16(d0[mt][2*ks+1][2], d0[mt][2*ks+1][3]));
            }
        }

        // ---------- PIPELINE: build + load NEXT tile's A fragments now ----------
        // (independent of layer-1/final below -> fills dependency stalls)
        float s8_n = 0.0f;
        if (hasNext) {
            s8_n = build_trig(smem, tid, r_n);
        }
        __syncwarp();   // own-warp trig rows visible for ldsm
        if (hasNext) {
            #pragma unroll
            for (int mt = 0; mt < 2; mt++) {
                int idxr = __shfl_sync(0xffffffffu, idx_n, (lane & 15) | (mt << 4));
                u32 rbase = sb + SM_EMB + (u32)idxr * EMB_STRIDE_B;
                int sw = idxr & 3;
                ldsm_x4(ah[mt][0][0], ah[mt][0][1], ah[mt][0][2], ah[mt][0][3],
                        rbase + (u32)((chunkSel ^ sw) * 16));
                ldsm_x4(ah[mt][1][0], ah[mt][1][1], ah[mt][1][2], ah[mt][1][3],
                        rbase + (u32)(((chunkSel + 2) ^ sw) * 16));
                ldsm_x4(ah[mt][2][0], ah[mt][2][1], ah[mt][2][2], ah[mt][2][3],
                        trigBase + (u32)(mt * 16 * TRIG_STRIDE_B));
            }
        }

        // ---------- layer 1: ks=0 bias-in-C (JIT), ks=1..3 accumulate ----------
        float d1[2][8][4];
        #pragma unroll
        for (int ntp = 0; ntp < 4; ntp++) {
            int off = ((0 * 4 + ntp) * 32 + lane) * 16;
            uint4 bh = *(const uint4*)(smem + SM_F1H + off);
            float2 bbA, bbB;
            asm("ld.shared.v2.f32 {%0, %1}, [%2];"
                : "=f"(bbA.x), "=f"(bbA.y) : "r"(biasB1 + (u32)(ntp * 64)));
            asm("ld.shared.v2.f32 {%0, %1}, [%2];"
                : "=f"(bbB.x), "=f"(bbB.y) : "r"(biasB1 + (u32)(ntp * 64 + 32)));
            #pragma unroll
            for (int mt = 0; mt < 2; mt++) {
                u32* a = ah1[mt][0];
                mma_fp16_c(d1[mt][2*ntp],   a[0], a[1], a[2], a[3], bh.x, bh.y,
                           bbA.x, bbA.y);
                mma_fp16_c(d1[mt][2*ntp+1], a[0], a[1], a[2], a[3], bh.z, bh.w,
                           bbB.x, bbB.y);
            }
        }
        #pragma unroll
        for (int ks = 1; ks < 4; ks++) {
            #pragma unroll
            for (int ntp = 0; ntp < 4; ntp++) {
                int off = ((ks * 4 + ntp) * 32 + lane) * 16;
                uint4 bh = *(const uint4*)(smem + SM_F1H + off);
                #pragma unroll
                for (int mt = 0; mt < 2; mt++) {
                    u32* a = ah1[mt][ks];
                    mma_fp16(d1[mt][2*ntp],   a[0], a[1], a[2], a[3], bh.x, bh.y);
                    mma_fp16(d1[mt][2*ntp+1], a[0], a[1], a[2], a[3], bh.z, bh.w);
                }
            }
        }

        // ---------- final: packed silu -> Wout dot ON TENSOR PIPE ----------
        #pragma unroll
        for (int mt = 0; mt < 2; mt++) {
            float dd[4];
            {
                u32 a0 = silu_pk(pk16(d1[mt][0][0], d1[mt][0][1]));
                u32 a1 = silu_pk(pk16(d1[mt][0][2], d1[mt][0][3]));
                u32 a2 = silu_pk(pk16(d1[mt][1][0], d1[mt][1][1]));
                u32 a3 = silu_pk(pk16(d1[mt][1][2], d1[mt][1][3]));
                mma_fp16_c(dd, a0, a1, a2, a3, wb[0][0], wb[0][1], outb, outb);
            }
            #pragma unroll
            for (int ks = 1; ks < 4; ks++) {
                u32 a0 = silu_pk(pk16(d1[mt][2*ks][0],   d1[mt][2*ks][1]));
                u32 a1 = silu_pk(pk16(d1[mt][2*ks][2],   d1[mt][2*ks][3]));
                u32 a2 = silu_pk(pk16(d1[mt][2*ks+1][0], d1[mt][2*ks+1][1]));
                u32 a3 = silu_pk(pk16(d1[mt][2*ks+1][2], d1[mt][2*ks+1][3]));
                mma_fp16(dd, a0, a1, a2, a3, wb[ks][0], wb[ks][1]);
            }
            // dd[0] = raw(row g), dd[2] = raw(row g+8)  (duplicated over t4)
            int rlT = mt * 16 + g;
            int rlB = rlT + 8;
            int tT = __shfl_sync(0xffffffffu, t_c, rlT);
            int tB = __shfl_sync(0xffffffffu, t_c, rlB);
            if (t4 == 0) {
                int pT = tile * M_TILE + rowA + rlT;
                int pB = tile * M_TILE + rowA + rlB;
                float thT = __fdividef(1.0f, 1.0f + __expf(-dd[0]));
                float thB = __fdividef(1.0f, 1.0f + __expf(-dd[2]));
                float oT = (tT == 0) ? (X_A0 * CSANMAX) : thT * CSANMAX;
                float oB = (tB == 0) ? (X_A0 * CSANMAX) : thB * CSANMAX;
                if (pT < n) outp[pT] = oT;
                if (pB < n) outp[pB] = oB;
            }
        }

        // rotate pipelined state
        t_c = t_n;
        s8_c = s8_n;
    }
}

extern "C" void kernel_launch(void* const* d_in, const int* in_sizes, int n_in,
                              void* d_out, int out_size)
{
    const int*   time_idx = (const int*)  d_in[0];
    const float* rho      = (const float*)d_in[1];
    const float* emb      = (const float*)d_in[2];
    const float* W0       = (const float*)d_in[3];
    const float* b0       = (const float*)d_in[4];
    const float* W1       = (const float*)d_in[5];
    const float* b1       = (const float*)d_in[6];
    const float* Wout     = (const float*)d_in[7];
    const float* bout     = (const float*)d_in[8];
    float* out = (float*)d_out;

    int n = in_sizes[0];
    int ntiles = (n + M_TILE - 1) / M_TILE;

    cudaFuncSetAttribute(slfm_hmma_kernel,
                         cudaFuncAttributeMaxDynamicSharedMemorySize, SM_TOTAL);
    int grid = ntiles < GRID_CTAS ? ntiles : GRID_CTAS;
    slfm_hmma_kernel<<<grid, TPB, SM_TOTAL>>>(time_idx, rho, emb, W0, b0, W1, b1,
                                              Wout, bout, out, n, ntiles);
}

// round 17
// speedup vs baseline: 1.0562x; 1.0069x over previous
#include <cuda_runtime.h>
#include <cuda_fp16.h>
#include <cstdint>
#include <math.h>

#define N_TIME   512
#define LATENT   32
#define HIDDEN   64
#define N_MODES  8
#define X_A0     0.3f
#define CSANMAX  28700.0f
#define BASE_LOGIT (-0.8472978603872034f)
#define PI_F 3.14159265358979323846f

#define TPB       128
#define M_TILE    128
#define GRID_CTAS 592

#define EMB_STRIDE_B  64
#define TRIG_STRIDE_B 48

// ---- smem layout (bytes) ----
#define SM_EMB  0                          // 511 * 64 -> pad 32768
#define SM_TRIG 32768                      // 128 * 48 = 6144
#define SM_F0H  (SM_TRIG + 6144)           // 38912, 3ks*4ntp*32*16 = 6144
#define SM_F1H  (SM_F0H + 6144)            // 45056, 4ks -> 8192
#define SM_B0   (SM_F1H + 8192)            // 53248
#define SM_B1   (SM_B0 + 256)
#define SM_WO   (SM_B1 + 256)
#define SM_W48  (SM_WO + 256)              // W0 row 48 (fp32)
#define SM_BO   (SM_W48 + 256)
#define SM_TOTAL (SM_BO + 16)              // ~53 KB -> 4 CTAs/SM

typedef uint32_t u32;

#define HALF2_HALF 0x38003800u   // fp16x2 {0.5, 0.5}

__device__ __forceinline__ u32 smem_u32(const void* p) {
    u32 a;
    asm("{ .reg .u64 t; cvta.to.shared.u64 t, %1; cvt.u32.u64 %0, t; }"
        : "=r"(a) : "l"(p));
    return a;
}

// pack two fp32 -> fp16x2, first arg in LOW half
__device__ __forceinline__ u32 pk16(float lo, float hi) {
    u32 r;
    asm("cvt.rn.f16x2.f32 %0, %1, %2;" : "=r"(r) : "f"(hi), "f"(lo));
    return r;
}

// packed silu on fp16x2: h = x * (0.5*tanh(0.5x) + 0.5). ONE MUFU per 2 elems.
__device__ __forceinline__ u32 silu_pk(u32 hx) {
    u32 t, th, s, r;
    asm("mul.f16x2 %0, %1, %2;" : "=r"(t)  : "r"(hx), "r"(HALF2_HALF));
    asm("tanh.approx.f16x2 %0, %1;" : "=r"(th) : "r"(t));
    asm("fma.rn.f16x2 %0, %1, %2, %3;" : "=r"(s) : "r"(th), "r"(HALF2_HALF), "r"(HALF2_HALF));
    asm("mul.f16x2 %0, %1, %2;" : "=r"(r) : "r"(hx), "r"(s));
    return r;
}

__device__ __forceinline__ void mma_fp16(float* d, u32 a0, u32 a1, u32 a2, u32 a3,
                                         u32 b0, u32 b1) {
    asm volatile("mma.sync.aligned.m16n8k16.row.col.f32.f16.f16.f32 "
                 "{%0,%1,%2,%3}, {%4,%5,%6,%7}, {%8,%9}, {%0,%1,%2,%3};"
                 : "+f"(d[0]), "+f"(d[1]), "+f"(d[2]), "+f"(d[3])
                 : "r"(a0), "r"(a1), "r"(a2), "r"(a3), "r"(b0), "r"(b1));
}

__device__ __forceinline__ void ldsm_x4(u32& r0, u32& r1, u32& r2, u32& r3, u32 addr) {
    asm volatile("ldmatrix.sync.aligned.m8n8.x4.shared.b16 {%0,%1,%2,%3}, [%4];"
                 : "=r"(r0), "=r"(r1), "=r"(r2), "=r"(r3) : "r"(addr));
}

// build trig features k=32..47 into trig smem row (tid), return sin(8*pi*rho)
// order: [rho, cos1..cos8, sin1..sin7]
// pi*rho in [0, pi) -> MUFU-direct __sinf/__cosf are accurate (no range reduction)
__device__ __forceinline__ float build_trig(char* smem, int tid, float r) {
    float xv[16];
    xv[0] = r;
    float a  = PI_F * r;
    float s1 = __sinf(a);
    float c1 = __cosf(a);
    float ck = c1, sk = s1;
    xv[1] = ck; xv[9] = sk;
    float s8 = s1;
    #pragma unroll
    for (int k = 2; k <= N_MODES; k++) {
        float cn = fmaf(ck, c1, -sk * s1);
        float sn = fmaf(sk, c1,  ck * s1);
        ck = cn; sk = sn;
        xv[k] = ck;
        if (k < 8) xv[8 + k] = sk;
        else       s8 = sk;
    }
    uint4 v0 = make_uint4(pk16(xv[0], xv[1]), pk16(xv[2], xv[3]),
                          pk16(xv[4], xv[5]), pk16(xv[6], xv[7]));
    uint4 v1 = make_uint4(pk16(xv[8], xv[9]), pk16(xv[10], xv[11]),
                          pk16(xv[12], xv[13]), pk16(xv[14], xv[15]));
    char* rowp = smem + SM_TRIG + tid * TRIG_STRIDE_B;
    *(uint4*)(rowp)      = v0;
    *(uint4*)(rowp + 16) = v1;
    return s8;
}

__global__ __launch_bounds__(TPB, 4)
void slfm_hmma_kernel(const int* __restrict__ time_idx,
                      const float* __restrict__ rho,
                      const float* __restrict__ emb,
                      const float* __restrict__ W0,
                      const float* __restrict__ b0g,
                      const float* __restrict__ W1,
                      const float* __restrict__ b1g,
                      const float* __restrict__ Woutg,
                      const float* __restrict__ boutg,
                      float* __restrict__ outp,
                      int n, int ntiles)
{
    extern __shared__ char smem[];
    const u32 sb = smem_u32(smem);
    const int tid  = threadIdx.x;
    const int lane = tid & 31;
    const int warp = tid >> 5;
    const int g    = lane >> 2;
    const int t4   = lane & 3;
    const int rowA = warp * 32;

    // ---- stage emb table as fp16: row stride 64B, chunk q stored at q^(row&3) ----
    for (int i = tid; i < (N_TIME - 1) * 4; i += TPB) {
        int row = i >> 2, q = i & 3;
        const float4* e = (const float4*)(emb + row * LATENT) + q * 2;
        float4 e0 = e[0], e1 = e[1];
        uint4 v = make_uint4(pk16(e0.x, e0.y), pk16(e0.z, e0.w),
                             pk16(e1.x, e1.y), pk16(e1.z, e1.w));
        int qs = q ^ (row & 3);   // bank swizzle
        *(uint4*)(smem + SM_EMB + row * EMB_STRIDE_B + qs * 16) = v;
    }

    // ---- stage fp16 weight fragments (hi only) ----
    for (int i = tid; i < 512; i += TPB) {
        int ks = i >> 7, ntp = (i >> 5) & 3, ln = i & 31;
        int gg = ln >> 2, tt = ln & 3;
        int k0 = ks * 16 + tt * 2;

        {   // layer 1, all ks
            u32 hh[4];
            #pragma unroll
            for (int sub = 0; sub < 2; sub++) {
                int nn = (ntp * 2 + sub) * 8 + gg;
                hh[sub*2+0] = pk16(W1[(k0    ) * HIDDEN + nn],
                                   W1[(k0 + 1) * HIDDEN + nn]);
                hh[sub*2+1] = pk16(W1[(k0 + 8) * HIDDEN + nn],
                                   W1[(k0 + 9) * HIDDEN + nn]);
            }
            int off = ((ks * 4 + ntp) * 32 + ln) * 16;
            *(uint4*)(smem + SM_F1H + off) = make_uint4(hh[0], hh[1], hh[2], hh[3]);
        }
        if (ks < 3) {   // layer 0, k = 0..47
            u32 hh[4];
            #pragma unroll
            for (int sub = 0; sub < 2; sub++) {
                int nn = (ntp * 2 + sub) * 8 + gg;
                hh[sub*2+0] = pk16(W0[(k0    ) * HIDDEN + nn],
                                   W0[(k0 + 1) * HIDDEN + nn]);
                hh[sub*2+1] = pk16(W0[(k0 + 8) * HIDDEN + nn],
                                   W0[(k0 + 9) * HIDDEN + nn]);
            }
            int off = ((ks * 4 + ntp) * 32 + ln) * 16;
            *(uint4*)(smem + SM_F0H + off) = make_uint4(hh[0], hh[1], hh[2], hh[3]);
        }
    }
    if (tid < HIDDEN) {
        ((float*)(smem + SM_B0))[tid] = b0g[tid];
        ((float*)(smem + SM_B1))[tid] = b1g[tid];
        ((float*)(smem + SM_WO))[tid] = Woutg[tid];
        ((float*)(smem + SM_W48))[tid] = W0[48 * HIDDEN + tid];
    }
    if (tid == 0) *((float*)(smem + SM_BO)) = boutg[0] + BASE_LOGIT;

    // trig ldmatrix base (static per lane)
    const u32 trigBase = sb + SM_TRIG +
        (u32)((rowA + (lane & 15)) * TRIG_STRIDE_B + (lane >> 4) * 16);
    const int chunkSel = lane >> 4;   // 0 or 1

    // ---- prologue: first tile point data + trig ----
    int tile = blockIdx.x;
    int t_c = 0, idx_c = 0;
    float s8_c = 0.0f;
    if (tile < ntiles) {
        int p = tile * M_TILE + tid;
        int ps = p < n ? p : n - 1;
        t_c = time_idx[ps];
        float r0 = rho[ps];
        idx_c = t_c - 1;
        idx_c = idx_c < 0 ? 0 : (idx_c > N_TIME - 2 ? N_TIME - 2 : idx_c);
        s8_c = build_trig(smem, tid, r0);
    }
    __syncthreads();   // staging + trig visible

    // ---- loop-invariant Wout B-fragments (replicated-dot trick) ----
    u32 wb[4][2];
    {
        const float* wo = (const float*)(smem + SM_WO);
        #pragma unroll
        for (int ks = 0; ks < 4; ks++) {
            int k0 = ks * 16 + t4 * 2;
            wb[ks][0] = pk16(wo[k0],     wo[k0 + 1]);
            wb[ks][1] = pk16(wo[k0 + 8], wo[k0 + 9]);
        }
    }
    const float outb = *((const float*)(smem + SM_BO));  // bout + BASE_LOGIT

    for (; tile < ntiles; tile += GRID_CTAS) {
        // ---------- next-tile LDGs (tiny) ----------
        int ntile2 = tile + GRID_CTAS;
        int   t_n = 0, idx_n = 0;
        float r_n = 0.0f;
        if (ntile2 < ntiles) {
            int p = ntile2 * M_TILE + tid;
            int ps = p < n ? p : n - 1;
            t_n = time_idx[ps];
            r_n = rho[ps];
            idx_n = t_n - 1;
            idx_n = idx_n < 0 ? 0 : (idx_n > N_TIME - 2 ? N_TIME - 2 : idx_n);
        }

        // ---------- layer 0: A from emb table (ks 0,1) + trig (ks 2) ----------
        float d0[2][8][4];
        #pragma unroll
        for (int nt = 0; nt < 8; nt++) {
            int n0 = nt * 8 + t4 * 2;
            float2 bb = *(const float2*)(smem + SM_B0 + n0 * 4);
            #pragma unroll
            for (int mt = 0; mt < 2; mt++) {
                d0[mt][nt][0] = bb.x; d0[mt][nt][1] = bb.y;
                d0[mt][nt][2] = bb.x; d0[mt][nt][3] = bb.y;
            }
        }

        u32 ah[2][3][4];
        #pragma unroll
        for (int mt = 0; mt < 2; mt++) {
            int idxr = __shfl_sync(0xffffffffu, idx_c, (lane & 15) | (mt << 4));
            u32 rbase = sb + SM_EMB + (u32)idxr * EMB_STRIDE_B;
            int sw = idxr & 3;
            u32 a0 = rbase + (u32)((chunkSel ^ sw) * 16);           // chunks 0,1
            u32 a1 = rbase + (u32)(((chunkSel + 2) ^ sw) * 16);     // chunks 2,3
            ldsm_x4(ah[mt][0][0], ah[mt][0][1], ah[mt][0][2], ah[mt][0][3], a0);
            ldsm_x4(ah[mt][1][0], ah[mt][1][1], ah[mt][1][2], ah[mt][1][3], a1);
            u32 tb = trigBase + (u32)(mt * 16 * TRIG_STRIDE_B);
            ldsm_x4(ah[mt][2][0], ah[mt][2][1], ah[mt][2][2], ah[mt][2][3], tb);
        }

        #pragma unroll
        for (int ks = 0; ks < 3; ks++) {
            #pragma unroll
            for (int ntp = 0; ntp < 4; ntp++) {
                int off = ((ks * 4 + ntp) * 32 + lane) * 16;
                uint4 bh = *(const uint4*)(smem + SM_F0H + off);
                #pragma unroll
                for (int mt = 0; mt < 2; mt++) {
                    u32* a = ah[mt][ks];
                    mma_fp16(d0[mt][2*ntp],   a[0], a[1], a[2], a[3], bh.x, bh.y);
                    mma_fp16(d0[mt][2*ntp+1], a[0], a[1], a[2], a[3], bh.z, bh.w);
                }
            }
        }
        __syncwarp();   // warp's trig reads complete -> trig rows dead

        // ---------- rebuild trig for next tile ----------
        float s8_n = 0.0f;
        if (ntile2 < ntiles) s8_n = build_trig(smem, tid, r_n);

        // ---------- k=48 rank-1 fix: d0 += sin(8*pi*rho_row) * W0[48][col] ----------
        #pragma unroll
        for (int mt = 0; mt < 2; mt++) {
            float s8T = __shfl_sync(0xffffffffu, s8_c, mt * 16 + g);
            float s8B = __shfl_sync(0xffffffffu, s8_c, mt * 16 + g + 8);
            #pragma unroll
            for (int nt = 0; nt < 8; nt++) {
                int n0 = nt * 8 + t4 * 2;
                float2 w48 = *(const float2*)(smem + SM_W48 + n0 * 4);
                d0[mt][nt][0] = fmaf(s8T, w48.x, d0[mt][nt][0]);
                d0[mt][nt][1] = fmaf(s8T, w48.y, d0[mt][nt][1]);
                d0[mt][nt][2] = fmaf(s8B, w48.x, d0[mt][nt][2]);
                d0[mt][nt][3] = fmaf(s8B, w48.y, d0[mt][nt][3]);
            }
        }

        // ---------- epilogue 0: pack -> PACKED silu (f16x2) -> layer-1 A frags ----------
        u32 ah1[2][4][4];
        #pragma unroll
        for (int mt = 0; mt < 2; mt++) {
            #pragma unroll
            for (int ks = 0; ks < 4; ks++) {
                ah1[mt][ks][0] = silu_pk(pk16(d0[mt][2*ks][0],   d0[mt][2*ks][1]));
                ah1[mt][ks][1] = silu_pk(pk16(d0[mt][2*ks][2],   d0[mt][2*ks][3]));
                ah1[mt][ks][2] = silu_pk(pk16(d0[mt][2*ks+1][0], d0[mt][2*ks+1][1]));
                ah1[mt][ks][3] = silu_pk(pk16(d0[mt][2*ks+1][2], d0[mt][2*ks+1][3]));
            }
        }

        // ---------- layer 1 (d1 init with b1) ----------
        float d1[2][8][4];
        #pragma unroll
        for (int nt = 0; nt < 8; nt++) {
            int n0 = nt * 8 + t4 * 2;
            float2 bb = *(const float2*)(smem + SM_B1 + n0 * 4);
            #pragma unroll
            for (int mt = 0; mt < 2; mt++) {
                d1[mt][nt][0] = bb.x; d1[mt][nt][1] = bb.y;
                d1[mt][nt][2] = bb.x; d1[mt][nt][3] = bb.y;
            }
        }

        #pragma unroll
        for (int ks = 0; ks < 4; ks++) {
            #pragma unroll
            for (int ntp = 0; ntp < 4; ntp++) {
                int off = ((ks * 4 + ntp) * 32 + lane) * 16;
                uint4 bh = *(const uint4*)(smem + SM_F1H + off);
                #pragma unroll
                for (int mt = 0; mt < 2; mt++) {
                    u32* a = ah1[mt][ks];
                    mma_fp16(d1[mt][2*ntp],   a[0], a[1], a[2], a[3], bh.x, bh.y);
                    mma_fp16(d1[mt][2*ntp+1], a[0], a[1], a[2], a[3], bh.z, bh.w);
                }
            }
        }

        // ---------- final: PACKED silu -> TWO independent Wout MMA chains ----------
        #pragma unroll
        for (int mt = 0; mt < 2; mt++) {
            float dda[4] = {outb, outb, outb, outb};
            float ddb[4] = {0.0f, 0.0f, 0.0f, 0.0f};
            #pragma unroll
            for (int ks = 0; ks < 4; ks++) {
                u32 a0 = silu_pk(pk16(d1[mt][2*ks][0],   d1[mt][2*ks][1]));
                u32 a1 = silu_pk(pk16(d1[mt][2*ks][2],   d1[mt][2*ks][3]));
                u32 a2 = silu_pk(pk16(d1[mt][2*ks+1][0], d1[mt][2*ks+1][1]));
                u32 a3 = silu_pk(pk16(d1[mt][2*ks+1][2], d1[mt][2*ks+1][3]));
                if (ks < 2) mma_fp16(dda, a0, a1, a2, a3, wb[ks][0], wb[ks][1]);
                else        mma_fp16(ddb, a0, a1, a2, a3, wb[ks][0], wb[ks][1]);
            }
            float rawT = dda[0] + ddb[0];   // row g
            float rawB = dda[2] + ddb[2];   // row g+8
            int rlT = mt * 16 + g;
            int rlB = rlT + 8;
            int tT = __shfl_sync(0xffffffffu, t_c, rlT);
            int tB = __shfl_sync(0xffffffffu, t_c, rlB);
            if (t4 == 0) {
                int pT = tile * M_TILE + rowA + rlT;
                int pB = tile * M_TILE + rowA + rlB;
                float thT = __fdividef(1.0f, 1.0f + __expf(-rawT));
                float thB = __fdividef(1.0f, 1.0f + __expf(-rawB));
                float oT = (tT == 0) ? (X_A0 * CSANMAX) : thT * CSANMAX;
                float oB = (tB == 0) ? (X_A0 * CSANMAX) : thB * CSANMAX;
                if (pT < n) outp[pT] = oT;
                if (pB < n) outp[pB] = oB;
            }
        }
        __syncwarp();
        t_c = t_n;
        idx_c = idx_n;
        s8_c = s8_n;
    }
}

extern "C" void kernel_launch(void* const* d_in, const int* in_sizes, int n_in,
                              void* d_out, int out_size)
{
    const int*   time_idx = (const int*)  d_in[0];
    const float* rho      = (const float*)d_in[1];
    const float* emb      = (const float*)d_in[2];
    const float* W0       = (const float*)d_in[3];
    const float* b0       = (const float*)d_in[4];
    const float* W1       = (const float*)d_in[5];
    const float* b1       = (const float*)d_in[6];
    const float* Wout     = (const float*)d_in[7];
    const float* bout     = (const float*)d_in[8];
    float* out = (float*)d_out;

    int n = in_sizes[0];
    int ntiles = (n + M_TILE - 1) / M_TILE;

    cudaFuncSetAttribute(slfm_hmma_kernel,
                         cudaFuncAttributeMaxDynamicSharedMemorySize, SM_TOTAL);
    int grid = ntiles < GRID_CTAS ? ntiles : GRID_CTAS;
    slfm_hmma_kernel<<<grid, TPB, SM_TOTAL>>>(time_idx, rho, emb, W0, b0, W1, b1,
                                              Wout, bout, out, n, ntiles);
}